// round 16
// baseline (speedup 1.0000x reference)
#include <cuda_runtime.h>
#include <cstdint>

// ---------------------------------------------------------------------------
// out = relu(x - x@P + z@P) with P = c c^T (rank-1, ||c|| = 1).
// u = P[k,:] (k = argmax of first 128 diag entries), pkk = P[k,k]:
//   alpha_b = ((z.u) - (x_b.u)) / pkk ;  out = relu(x + alpha_b * u)
//
// Persistent-block version: 296 blocks (2/SM, single wave) pull row-PAIRS
// from a global atomic counter. Per-block startup (pivot, u regs, z.u) is
// paid once and amortized over ~3.5 pairs. The loop is software-pipelined:
// next pair's x loads are issued a full iteration ahead of use, covering L2
// latency; one barrier per iteration; double-buffered smem.
// Scheduling is non-deterministic but output is per-row with fixed-order
// reductions -> bit-identical regardless of which block does which row.
// A trailing kernel re-zeros the counter so every graph replay is identical.
// ---------------------------------------------------------------------------

__device__ unsigned g_ctr = 0;

__global__ void reset_ctr_kernel() { g_ctr = 0u; }

__device__ __forceinline__ float dot8(float4 a0, float4 a1, float4 u0, float4 u1) {
    return (fmaf(a0.x, u0.x, a0.y * u0.y) + fmaf(a0.z, u0.z, a0.w * u0.w)) +
           (fmaf(a1.x, u1.x, a1.y * u1.y) + fmaf(a1.z, u1.z, a1.w * u1.w));
}

// Specialized: D == 4096 (n4 = 1024); thread owns cols t and t+512.
__global__ void __launch_bounds__(512, 2)
pcav_persist_kernel(const float* __restrict__ x, const float* __restrict__ P,
                    const float* __restrict__ z, float* __restrict__ out,
                    int B) {
    const int D = 4096;
    __shared__ float    s_red[2][16][2];
    __shared__ float    s_zred[16];
    __shared__ unsigned s_next[2];
    __shared__ int      s_k;
    __shared__ float    s_inv;

    const int t    = threadIdx.x;
    const int lane = t & 31;
    const int wid  = t >> 5;
    const int j0 = t, j1 = t + 512;
    const unsigned npairs = (unsigned)((B + 1) >> 1);

    // ---- front-batched z loads (pivot-independent) ----
    const float4* __restrict__ z4 = reinterpret_cast<const float4*>(z);
    const float4 zz0 = z4[j0];
    const float4 zz1 = z4[j1];

    // ---- pivot: warp 0; first two work grabs: thread 0 ----
    if (wid == 0) {
        float best = -3.0e38f;
        int   bi   = 0;
        #pragma unroll
        for (int r = 0; r < 4; r++) {
            const int i = r * 32 + lane;
            float v = P[(size_t)i * D + i];
            if (v > best) { best = v; bi = i; }
        }
        #pragma unroll
        for (int o = 16; o > 0; o >>= 1) {
            float ov = __shfl_xor_sync(0xffffffffu, best, o);
            int   oi = __shfl_xor_sync(0xffffffffu, bi,   o);
            if (ov > best || (ov == best && oi < bi)) { best = ov; bi = oi; }
        }
        if (lane == 0) { s_k = bi; s_inv = 1.0f / best; }
    }
    if (t == 0) {
        s_next[0] = atomicAdd(&g_ctr, 1u);
        s_next[1] = atomicAdd(&g_ctr, 1u);
    }
    __syncthreads();                                  // bar A
    const int   k    = s_k;
    const float inv  = s_inv;
    unsigned    cur  = s_next[0];                     // read BEFORE bar B:
    unsigned    nxt  = s_next[1];                     // separates from loop writes

    // ---- u held in registers for the whole block ----
    const float4* __restrict__ u4 = reinterpret_cast<const float4*>(P + (size_t)k * D);
    const float4 u0 = u4[j0];
    const float4 u1 = u4[j1];

    // ---- z.u reduced once per block (dedicated smem, fixed order) ----
    float zp = dot8(zz0, zz1, u0, u1);
    #pragma unroll
    for (int o = 16; o > 0; o >>= 1)
        zp += __shfl_xor_sync(0xffffffffu, zp, o);
    if (lane == 0) s_zred[wid] = zp;
    __syncthreads();                                  // bar B
    float zu = 0.0f;
    #pragma unroll
    for (int w = 0; w < 16; w++) zu += s_zred[w];

    if (cur >= npairs) return;                        // uniform per block

    // ---- prologue: load current pair ----
    int row0 = (int)(cur * 2u);
    int row1 = row0 + 1;
    int r1c  = (row1 < B) ? row1 : row0;
    const float4* xr0 = reinterpret_cast<const float4*>(x + (size_t)row0 * D);
    const float4* xr1 = reinterpret_cast<const float4*>(x + (size_t)r1c  * D);
    float4 a00 = xr0[j0], a01 = xr0[j1];
    float4 a10 = xr1[j0], a11 = xr1[j1];

    int buf = 0;
    for (;;) {
        const bool havenext = (nxt < npairs);         // uniform

        // ---- prefetch next pair FIRST (full iteration to complete) ----
        float4 b00, b01, b10, b11;
        if (havenext) {
            const int nrow0 = (int)(nxt * 2u);
            const int nrow1 = nrow0 + 1;
            const int nr1c  = (nrow1 < B) ? nrow1 : nrow0;
            const float4* nx0 = reinterpret_cast<const float4*>(x + (size_t)nrow0 * D);
            const float4* nx1 = reinterpret_cast<const float4*>(x + (size_t)nr1c  * D);
            b00 = nx0[j0]; b01 = nx0[j1];
            b10 = nx1[j0]; b11 = nx1[j1];
        }
        if (t == 0) s_next[buf] = atomicAdd(&g_ctr, 1u);   // grab pair after next

        // ---- dots for current pair ----
        float p1 = dot8(a00, a01, u0, u1);
        float p2 = dot8(a10, a11, u0, u1);
        #pragma unroll
        for (int o = 16; o > 0; o >>= 1) {
            p1 += __shfl_xor_sync(0xffffffffu, p1, o);
            p2 += __shfl_xor_sync(0xffffffffu, p2, o);
        }
        if (lane == 0) { s_red[buf][wid][0] = p1; s_red[buf][wid][1] = p2; }
        __syncthreads();                              // the ONE barrier per iter

        float v1 = 0.0f, v2 = 0.0f;
        #pragma unroll
        for (int w = 0; w < 16; w++) {
            v1 += s_red[buf][w][0];
            v2 += s_red[buf][w][1];
        }
        const unsigned nn = s_next[buf];
        const float alpha0 = (zu - v1) * inv;
        const float alpha1 = (zu - v2) * inv;

        // ---- store current pair (fire-and-forget) ----
        {
            float4* orow0 = reinterpret_cast<float4*>(out + (size_t)row0 * D);
            float4 o0, o1;
            o0.x = fmaxf(fmaf(alpha0, u0.x, a00.x), 0.0f);
            o0.y = fmaxf(fmaf(alpha0, u0.y, a00.y), 0.0f);
            o0.z = fmaxf(fmaf(alpha0, u0.z, a00.z), 0.0f);
            o0.w = fmaxf(fmaf(alpha0, u0.w, a00.w), 0.0f);
            o1.x = fmaxf(fmaf(alpha0, u1.x, a01.x), 0.0f);
            o1.y = fmaxf(fmaf(alpha0, u1.y, a01.y), 0.0f);
            o1.z = fmaxf(fmaf(alpha0, u1.z, a01.z), 0.0f);
            o1.w = fmaxf(fmaf(alpha0, u1.w, a01.w), 0.0f);
            orow0[j0] = o0;
            orow0[j1] = o1;
            if (row1 < B) {
                float4* orow1 = reinterpret_cast<float4*>(out + (size_t)row1 * D);
                float4 q0, q1;
                q0.x = fmaxf(fmaf(alpha1, u0.x, a10.x), 0.0f);
                q0.y = fmaxf(fmaf(alpha1, u0.y, a10.y), 0.0f);
                q0.z = fmaxf(fmaf(alpha1, u0.z, a10.z), 0.0f);
                q0.w = fmaxf(fmaf(alpha1, u0.w, a10.w), 0.0f);
                q1.x = fmaxf(fmaf(alpha1, u1.x, a11.x), 0.0f);
                q1.y = fmaxf(fmaf(alpha1, u1.y, a11.y), 0.0f);
                q1.z = fmaxf(fmaf(alpha1, u1.z, a11.z), 0.0f);
                q1.w = fmaxf(fmaf(alpha1, u1.w, a11.w), 0.0f);
                orow1[j0] = q0;
                orow1[j1] = q1;
            }
        }

        if (!havenext) break;                         // uniform

        // ---- rotate pipeline state ----
        a00 = b00; a01 = b01; a10 = b10; a11 = b11;
        cur = nxt;
        row0 = (int)(cur * 2u);
        row1 = row0 + 1;
        nxt = nn;
        buf ^= 1;
    }
}

// ---- generic fallback (any D multiple of 4, any B): fused one-row ----
__global__ void __launch_bounds__(512, 4)
pcav_generic_kernel(const float* __restrict__ x, const float* __restrict__ P,
                    const float* __restrict__ z, float* __restrict__ out, int D) {
    __shared__ float s_part[16];
    __shared__ int   s_k;
    __shared__ float s_inv;
    __shared__ float s_alpha;

    const int t    = threadIdx.x;
    const int lane = t & 31;
    const int wid  = t >> 5;

    if (wid == 0) {
        float best = -3.0e38f;
        int   bi   = 0;
        #pragma unroll
        for (int r = 0; r < 4; r++) {
            const int i = r * 32 + lane;
            if (i < D) {
                float v = P[(size_t)i * D + i];
                if (v > best) { best = v; bi = i; }
            }
        }
        #pragma unroll
        for (int o = 16; o > 0; o >>= 1) {
            float ov = __shfl_xor_sync(0xffffffffu, best, o);
            int   oi = __shfl_xor_sync(0xffffffffu, bi,   o);
            if (ov > best || (ov == best && oi < bi)) { best = ov; bi = oi; }
        }
        if (lane == 0) { s_k = bi; s_inv = 1.0f / best; }
    }
    __syncthreads();
    const int   k   = s_k;
    const float inv = s_inv;

    const size_t row_off = (size_t)blockIdx.x * (size_t)D;
    const float4* __restrict__ xr = reinterpret_cast<const float4*>(x + row_off);
    const float4* __restrict__ u4 = reinterpret_cast<const float4*>(P + (size_t)k * D);
    const float4* __restrict__ z4 = reinterpret_cast<const float4*>(z);
    float4* __restrict__ orow     = reinterpret_cast<float4*>(out + row_off);
    const int n4 = D >> 2;

    float part = 0.0f;
    for (int j = t; j < n4; j += 512) {
        float4 a = xr[j], u = u4[j], zz = z4[j];
        part = fmaf(zz.x - a.x, u.x, part);
        part = fmaf(zz.y - a.y, u.y, part);
        part = fmaf(zz.z - a.z, u.z, part);
        part = fmaf(zz.w - a.w, u.w, part);
    }
    #pragma unroll
    for (int o = 16; o > 0; o >>= 1)
        part += __shfl_xor_sync(0xffffffffu, part, o);
    if (lane == 0) s_part[wid] = part;
    __syncthreads();
    if (wid == 0) {
        float v = (lane < 16) ? s_part[lane] : 0.0f;
        #pragma unroll
        for (int o = 8; o > 0; o >>= 1)
            v += __shfl_xor_sync(0xffffffffu, v, o);
        if (lane == 0) s_alpha = v * inv;
    }
    __syncthreads();
    const float alpha = s_alpha;

    for (int j = t; j < n4; j += 512) {
        float4 a = xr[j], u = u4[j], o;
        o.x = fmaxf(fmaf(alpha, u.x, a.x), 0.0f);
        o.y = fmaxf(fmaf(alpha, u.y, a.y), 0.0f);
        o.z = fmaxf(fmaf(alpha, u.z, a.z), 0.0f);
        o.w = fmaxf(fmaf(alpha, u.w, a.w), 0.0f);
        orow[j] = o;
    }
}

extern "C" void kernel_launch(void* const* d_in, const int* in_sizes, int n_in,
                              void* d_out, int out_size) {
    // Identify inputs by element count: z = smallest (D), projection = D*D, x = B*D
    int zi = 0;
    for (int i = 1; i < n_in; i++)
        if (in_sizes[i] < in_sizes[zi]) zi = i;
    const int D = in_sizes[zi];

    int pi = -1, xi = -1;
    for (int i = 0; i < n_in; i++) {
        if (i == zi) continue;
        if ((long long)in_sizes[i] == (long long)D * (long long)D && pi < 0) pi = i;
        else xi = i;
    }
    if (pi < 0 || xi < 0) { xi = 0; pi = 1; }

    const float* x = (const float*)d_in[xi];
    const float* P = (const float*)d_in[pi];
    const float* z = (const float*)d_in[zi];
    float* out = (float*)d_out;

    const int B = in_sizes[xi] / D;

    if (D == 4096) {
        pcav_persist_kernel<<<296, 512>>>(x, P, z, out, B);
        reset_ctr_kernel<<<1, 1>>>();   // counter back to 0 for next replay
    } else {
        pcav_generic_kernel<<<B, 512>>>(x, P, z, out, D);
    }
}